// round 4
// baseline (speedup 1.0000x reference)
#include <cuda_runtime.h>
#include <stdint.h>

#define NUM_NODES 100000
#define NUM_EDGES 400000
#define MAXR      20          // Boruvka bound; early-exit typically ~8 rounds
#define BLOCKS    148
#define TPB       1024
#define NT        (BLOCKS * TPB)

typedef unsigned long long u64;

// Scratch (__device__ globals; no allocs allowed)
__device__ u64      g_key[NUM_EDGES];     // 51-bit order key: score32<<19 | (524287-e)
__device__ int      g_label[NUM_NODES];
__device__ u64      g_best[NUM_NODES];    // tagged: (round+1)<<51 | key51
__device__ u64      g_wl[2][NUM_EDGES];   // packed survivors: e<<34 | ra<<17 | rb
__device__ int      g_cnt[MAXR];
__device__ int      g_changed[MAXR];
__device__ unsigned g_count = 0;          // barrier arrivals
__device__ unsigned g_gen   = 0;          // barrier generation (wrap-safe across replays)

// ---- software grid barrier (validated pattern from R2: rel_err 0.0) ----
__device__ __forceinline__ unsigned ld_acq(const unsigned* p) {
    unsigned v;
    asm volatile("ld.acquire.gpu.u32 %0, [%1];" : "=r"(v) : "l"(p) : "memory");
    return v;
}
__device__ __forceinline__ void st_rel(unsigned* p, unsigned v) {
    asm volatile("st.release.gpu.u32 [%0], %1;" :: "l"(p), "r"(v) : "memory");
}
__device__ __forceinline__ void gbar() {
    __syncthreads();
    if (threadIdx.x == 0) {
        unsigned my = ld_acq(&g_gen);
        __threadfence();
        unsigned a = atomicAdd(&g_count, 1u);
        if (a == BLOCKS - 1) {
            g_count = 0;
            __threadfence();
            st_rel(&g_gen, my + 1u);
        } else {
            while (ld_acq(&g_gen) == my) __nanosleep(32);
        }
    }
    __syncthreads();
}

// find with path compression (phase A only; no hooks concurrent -> root stable,
// shortcut writes are benign/monotone)
__device__ __forceinline__ int find_compress(int v) {
    int p = g_label[v];
    if (p == v) return v;
    int root = p, q = g_label[root];
    while (q != root) { root = q; q = g_label[root]; }
    if (p != root) g_label[v] = root;
    return root;
}

// read-only find (phase B: concurrent hooks; races analyzed safe)
__device__ __forceinline__ int find_ro(int v) {
    int root = g_label[v];
    int q = g_label[root];
    while (q != root) { root = q; q = g_label[root]; }
    return root;
}

__global__ void __launch_bounds__(TPB, 1)
boruvka_kernel(const float* __restrict__ s,
               const float* __restrict__ u,
               const int*   __restrict__ src,
               const int*   __restrict__ dst,
               float*       __restrict__ out)
{
    const int tid  = blockIdx.x * TPB + threadIdx.x;
    const int lane = threadIdx.x & 31;

    // ---- init: keys (bitwise-match JAX f32 pipeline), labels, best, output ----
    for (int i = tid; i < NUM_EDGES; i += NT) {
        float sp = 1.0f / (1.0f + expf(-s[i]));
        float gb = -logf(-logf(u[i] + 1e-9f) + 1e-9f);
        unsigned ub = __float_as_uint(sp + gb);
        ub = (ub & 0x80000000u) ? ~ub : (ub | 0x80000000u);   // order-preserving
        g_key[i] = ((u64)ub << 19) | (u64)(524287 - i);       // ties -> lowest idx
        out[i] = 0.0f;
    }
    for (int i = tid; i < NUM_NODES; i += NT) {
        g_label[i] = i;
        g_best[i]  = 0ULL;     // stale tags from prior replay must be cleared
    }
    if (tid < MAXR) { g_cnt[tid] = 0; g_changed[tid] = 0; }
    gbar();

    int n = NUM_EDGES;
    for (int r = 0; r < MAXR; ++r) {
        const u64 tag = ((u64)(r + 1)) << 51;
        const u64* __restrict__ win  = g_wl[(r + 1) & 1];   // == g_wl[(r-1)&1]
        u64* __restrict__       wout = g_wl[r & 1];

        // ---- phase A: find roots, pick per-component max edge, compact ----
        const int npad = (n + 31) & ~31;   // warp-uniform trip counts for ballot
        for (int k = tid; k < npad; k += NT) {
            bool live = false; int e = 0, ra = 0, rb = 0;
            if (k < n) {
                if (r == 0) { e = k; ra = src[k]; rb = dst[k]; }
                else {
                    u64 w = win[k];
                    e  = (int)(w >> 34);
                    ra = (int)((w >> 17) & 0x1FFFF);
                    rb = (int)(w & 0x1FFFF);
                }
                ra = find_compress(ra);
                rb = find_compress(rb);
                if (ra != rb) {
                    live = true;
                    u64 kv = tag | g_key[e];
                    atomicMax(&g_best[ra], kv);
                    atomicMax(&g_best[rb], kv);
                }
            }
            unsigned m = __ballot_sync(0xffffffffu, live);
            if (m) {
                int leader = __ffs(m) - 1;
                int base = 0;
                if (lane == leader) base = atomicAdd(&g_cnt[r], __popc(m));
                base = __shfl_sync(0xffffffffu, base, leader);
                if (live)
                    wout[base + __popc(m & ((1u << lane) - 1))] =
                        ((u64)e << 34) | ((u64)ra << 17) | (u64)rb;
            }
        }
        gbar();

        // ---- phase B: hook roots along their best edge, mark accepted ----
        bool hooked = false;
        for (int i = tid; i < NUM_NODES; i += NT) {
            u64 bk = g_best[i];
            if ((bk >> 51) != (u64)(r + 1)) continue;   // stale / non-root
            int e  = 524287 - (int)(bk & 0x7FFFFULL);
            int lu = find_ro(src[e]);
            int lv = find_ro(dst[e]);
            int other = lu ^ lv ^ i;    // own-side chase ends at i (no self-hook yet)
            if (other == i) continue;   // mutual partner already hooked into us
            if (g_best[other] == bk) {
                // mutual 2-cycle: only larger-id root hooks; edge marked once
                if (i > other) { g_label[i] = other; out[e] = 1.0f; hooked = true; }
            } else {
                g_label[i] = other; out[e] = 1.0f; hooked = true;
            }
        }
        if (hooked) g_changed[r] = 1;
        gbar();

        if (!g_changed[r]) break;   // uniform: converged (forest complete)
        n = g_cnt[r];
        if (n == 0) break;
    }
}

extern "C" void kernel_launch(void* const* d_in, const int* in_sizes, int n_in,
                              void* d_out, int out_size)
{
    const float* s   = (const float*)d_in[0];
    const float* u   = (const float*)d_in[1];
    const int*   ei  = (const int*)d_in[2];   // [2, E] row-major
    const int*   src = ei;
    const int*   dst = ei + NUM_EDGES;
    float*       out = (float*)d_out;

    boruvka_kernel<<<BLOCKS, TPB>>>(s, u, src, dst, out);
}